// round 4
// baseline (speedup 1.0000x reference)
#include <cuda_runtime.h>
#include <cuda_bf16.h>
#include <math.h>

#define BATCH 256
#define NPTS  8192
#define CLAMP_V 10.0f

// Scratch (no allocations allowed -> __device__ globals)
__device__ float d_sums[BATCH * 15];   // per batch: sumA[3], sumB[3], M[3x3]=sum p_i q_j
__device__ float d_RT[BATCH * 12];     // per batch: R row-major [9], t [3]
__device__ float d_partial[BATCH];     // per-batch clamped-distance sums

__device__ __forceinline__ float warpSum(float v) {
#pragma unroll
    for (int o = 16; o; o >>= 1) v += __shfl_down_sync(0xffffffffu, v, o);
    return v;
}

// ---------------------------------------------------------------------------
// Kernel 1: per-batch reduction of 15 covariance/sum terms.
// One block per batch, 512 threads, float4-vectorized loads (4 points / chunk).
// ---------------------------------------------------------------------------
__global__ __launch_bounds__(512) void k1_cov(const float* __restrict__ pred,
                                              const float* __restrict__ truep) {
    const int b = blockIdx.x;
    const float* pp = pred  + (size_t)b * NPTS * 3;
    const float* qq = truep + (size_t)b * NPTS * 3;

    float sA0=0.f,sA1=0.f,sA2=0.f,sB0=0.f,sB1=0.f,sB2=0.f;
    float m00=0.f,m01=0.f,m02=0.f,m10=0.f,m11=0.f,m12=0.f,m20=0.f,m21=0.f,m22=0.f;

    const int nCh = (NPTS * 3) / 12;  // 2048 chunks of 4 points
    for (int c = threadIdx.x; c < nCh; c += blockDim.x) {
        const float4* vp = reinterpret_cast<const float4*>(pp + c * 12);
        const float4* vq = reinterpret_cast<const float4*>(qq + c * 12);
        float4 a0 = vp[0], a1 = vp[1], a2 = vp[2];
        float4 b0 = vq[0], b1 = vq[1], b2 = vq[2];
        float px[4] = {a0.x, a0.w, a1.z, a2.y};
        float py[4] = {a0.y, a1.x, a1.w, a2.z};
        float pz[4] = {a0.z, a1.y, a2.x, a2.w};
        float qx[4] = {b0.x, b0.w, b1.z, b2.y};
        float qy[4] = {b0.y, b1.x, b1.w, b2.z};
        float qz[4] = {b0.z, b1.y, b2.x, b2.w};
#pragma unroll
        for (int i = 0; i < 4; i++) {
            sA0 += px[i]; sA1 += py[i]; sA2 += pz[i];
            sB0 += qx[i]; sB1 += qy[i]; sB2 += qz[i];
            m00 += px[i]*qx[i]; m01 += px[i]*qy[i]; m02 += px[i]*qz[i];
            m10 += py[i]*qx[i]; m11 += py[i]*qy[i]; m12 += py[i]*qz[i];
            m20 += pz[i]*qx[i]; m21 += pz[i]*qy[i]; m22 += pz[i]*qz[i];
        }
    }

    __shared__ float ws[16][15];
    float vals[15] = {sA0,sA1,sA2,sB0,sB1,sB2,m00,m01,m02,m10,m11,m12,m20,m21,m22};
    const int lane = threadIdx.x & 31, w = threadIdx.x >> 5;
#pragma unroll
    for (int q = 0; q < 15; q++) {
        float r = warpSum(vals[q]);
        if (lane == 0) ws[w][q] = r;
    }
    __syncthreads();
    if (threadIdx.x < 15) {
        float tot = 0.f;
#pragma unroll
        for (int i = 0; i < 16; i++) tot += ws[i][threadIdx.x];
        d_sums[b * 15 + threadIdx.x] = tot;
    }
}

// ---------------------------------------------------------------------------
// Kernel 2: per-batch 3x3 Kabsch solve. One thread per batch, fp64 Jacobi
// eigendecomposition of K = H^T H -> V, sigma; U columns = H v / sigma.
// R = sum_k s_k v_k u_k^T (sign flip on smallest sigma iff det(H) < 0),
// matching the reference's  R = V diag(1,1,s) U^T.
// ---------------------------------------------------------------------------
__global__ void k2_kabsch() {
    const int b = blockIdx.x * blockDim.x + threadIdx.x;
    if (b >= BATCH) return;

    float s[15];
#pragma unroll
    for (int i = 0; i < 15; i++) s[i] = d_sums[b * 15 + i];

    const double invN = 1.0 / (double)NPTS;
    double sA[3] = {s[0], s[1], s[2]};
    double sB[3] = {s[3], s[4], s[5]};
    double H[3][3];
#pragma unroll
    for (int i = 0; i < 3; i++)
#pragma unroll
        for (int j = 0; j < 3; j++)
            H[i][j] = (double)s[6 + i * 3 + j] - sA[i] * sB[j] * invN;

    // K = H^T H  (symmetric PSD)
    double K[3][3];
#pragma unroll
    for (int i = 0; i < 3; i++)
#pragma unroll
        for (int j = 0; j < 3; j++)
            K[i][j] = H[0][i]*H[0][j] + H[1][i]*H[1][j] + H[2][i]*H[2][j];

    // Jacobi eigendecomposition: K = V Lam V^T
    double V[3][3] = {{1,0,0},{0,1,0},{0,0,1}};
    const int PP[3] = {0, 0, 1};
    const int QQ[3] = {1, 2, 2};
    for (int sweep = 0; sweep < 12; sweep++) {
#pragma unroll
        for (int pair = 0; pair < 3; pair++) {
            const int p = PP[pair], q = QQ[pair];
            double apq = K[p][q];
            if (fabs(apq) <= 1e-15 * (fabs(K[p][p]) + fabs(K[q][q]))) continue;
            double theta = (K[q][q] - K[p][p]) / (2.0 * apq);
            double t = (theta >= 0.0) ? 1.0 / (theta + sqrt(1.0 + theta * theta))
                                      : 1.0 / (theta - sqrt(1.0 + theta * theta));
            double c = 1.0 / sqrt(1.0 + t * t);
            double sn = t * c;
#pragma unroll
            for (int k = 0; k < 3; k++) {   // K <- K J (columns p,q)
                double kp = K[k][p], kq = K[k][q];
                K[k][p] = c * kp - sn * kq;
                K[k][q] = sn * kp + c * kq;
            }
#pragma unroll
            for (int k = 0; k < 3; k++) {   // K <- J^T K (rows p,q)
                double pk = K[p][k], qk = K[q][k];
                K[p][k] = c * pk - sn * qk;
                K[q][k] = sn * pk + c * qk;
            }
#pragma unroll
            for (int k = 0; k < 3; k++) {   // V <- V J
                double vp_ = V[k][p], vq_ = V[k][q];
                V[k][p] = c * vp_ - sn * vq_;
                V[k][q] = sn * vp_ + c * vq_;
            }
        }
    }

    double lam[3] = {K[0][0], K[1][1], K[2][2]};
    int imin = 0;
    if (lam[1] < lam[imin]) imin = 1;
    if (lam[2] < lam[imin]) imin = 2;

    double detH = H[0][0]*(H[1][1]*H[2][2] - H[1][2]*H[2][1])
                - H[0][1]*(H[1][0]*H[2][2] - H[1][2]*H[2][0])
                + H[0][2]*(H[1][0]*H[2][1] - H[1][1]*H[2][0]);

    double R[3][3] = {{0,0,0},{0,0,0},{0,0,0}};
#pragma unroll
    for (int k = 0; k < 3; k++) {
        double v0 = V[0][k], v1 = V[1][k], v2 = V[2][k];
        double hv[3];
#pragma unroll
        for (int i = 0; i < 3; i++)
            hv[i] = H[i][0]*v0 + H[i][1]*v1 + H[i][2]*v2;   // sigma * u_k
        double sig = sqrt(fmax(lam[k], 1e-300));
        double coef = 1.0 / sig;
        if (k == imin && detH < 0.0) coef = -coef;
        R[0][0] += coef * v0 * hv[0]; R[0][1] += coef * v0 * hv[1]; R[0][2] += coef * v0 * hv[2];
        R[1][0] += coef * v1 * hv[0]; R[1][1] += coef * v1 * hv[1]; R[1][2] += coef * v1 * hv[2];
        R[2][0] += coef * v2 * hv[0]; R[2][1] += coef * v2 * hv[1]; R[2][2] += coef * v2 * hv[2];
    }

    double cA[3] = {sA[0]*invN, sA[1]*invN, sA[2]*invN};
    double cB[3] = {sB[0]*invN, sB[1]*invN, sB[2]*invN};
    double t0 = cB[0] - (R[0][0]*cA[0] + R[0][1]*cA[1] + R[0][2]*cA[2]);
    double t1 = cB[1] - (R[1][0]*cA[0] + R[1][1]*cA[1] + R[1][2]*cA[2]);
    double t2 = cB[2] - (R[2][0]*cA[0] + R[2][1]*cA[1] + R[2][2]*cA[2]);

    float* rt = &d_RT[b * 12];
#pragma unroll
    for (int i = 0; i < 3; i++)
#pragma unroll
        for (int j = 0; j < 3; j++)
            rt[i * 3 + j] = (float)R[i][j];
    rt[9] = (float)t0; rt[10] = (float)t1; rt[11] = (float)t2;
}

// ---------------------------------------------------------------------------
// Kernel 3: apply (R, t), compute clamped distances, per-batch sum.
// aligned_j = sum_i p_i * R[i][j] + t[j]   (pred @ R, as in reference)
// ---------------------------------------------------------------------------
__global__ __launch_bounds__(512) void k3_dist(const float* __restrict__ pred,
                                               const float* __restrict__ truep) {
    const int b = blockIdx.x;
    __shared__ float sRT[12];
    if (threadIdx.x < 12) sRT[threadIdx.x] = d_RT[b * 12 + threadIdx.x];
    __syncthreads();
    const float R00=sRT[0], R01=sRT[1], R02=sRT[2],
                R10=sRT[3], R11=sRT[4], R12=sRT[5],
                R20=sRT[6], R21=sRT[7], R22=sRT[8],
                t0 =sRT[9], t1 =sRT[10], t2 =sRT[11];

    const float* pp = pred  + (size_t)b * NPTS * 3;
    const float* qq = truep + (size_t)b * NPTS * 3;

    float acc = 0.f;
    const int nCh = (NPTS * 3) / 12;
    for (int c = threadIdx.x; c < nCh; c += blockDim.x) {
        const float4* vp = reinterpret_cast<const float4*>(pp + c * 12);
        const float4* vq = reinterpret_cast<const float4*>(qq + c * 12);
        float4 a0 = vp[0], a1 = vp[1], a2 = vp[2];
        float4 b0 = vq[0], b1 = vq[1], b2 = vq[2];
        float px[4] = {a0.x, a0.w, a1.z, a2.y};
        float py[4] = {a0.y, a1.x, a1.w, a2.z};
        float pz[4] = {a0.z, a1.y, a2.x, a2.w};
        float qx[4] = {b0.x, b0.w, b1.z, b2.y};
        float qy[4] = {b0.y, b1.x, b1.w, b2.z};
        float qz[4] = {b0.z, b1.y, b2.x, b2.w};
#pragma unroll
        for (int i = 0; i < 4; i++) {
            float dx = px[i]*R00 + py[i]*R10 + pz[i]*R20 + t0 - qx[i];
            float dy = px[i]*R01 + py[i]*R11 + pz[i]*R21 + t1 - qy[i];
            float dz = px[i]*R02 + py[i]*R12 + pz[i]*R22 + t2 - qz[i];
            float d = sqrtf(dx*dx + dy*dy + dz*dz);
            acc += fminf(d, CLAMP_V);
        }
    }

    __shared__ float ws[16];
    const int lane = threadIdx.x & 31, w = threadIdx.x >> 5;
    float r = warpSum(acc);
    if (lane == 0) ws[w] = r;
    __syncthreads();
    if (w == 0) {
        float t = (lane < 16) ? ws[lane] : 0.f;
        t = warpSum(t);
        if (lane == 0) d_partial[b] = t;
    }
}

// ---------------------------------------------------------------------------
// Kernel 4: deterministic final reduce of 256 partials -> scalar mean.
// ---------------------------------------------------------------------------
__global__ void k4_final(float* __restrict__ out) {
    float v = d_partial[threadIdx.x];   // launched with exactly 256 threads
    __shared__ float ws[8];
    const int lane = threadIdx.x & 31, w = threadIdx.x >> 5;
    float r = warpSum(v);
    if (lane == 0) ws[w] = r;
    __syncthreads();
    if (threadIdx.x == 0) {
        float tot = 0.f;
#pragma unroll
        for (int i = 0; i < 8; i++) tot += ws[i];
        out[0] = tot / ((float)BATCH * (float)NPTS);
    }
}

extern "C" void kernel_launch(void* const* d_in, const int* in_sizes, int n_in,
                              void* d_out, int out_size) {
    // Inputs in metadata order: pred_frames, true_frames, pred_pos, true_pos.
    // Robustly select the two [B,N,3] arrays (size B*N*3) in order.
    const int POS_ELEMS = BATCH * NPTS * 3;
    const float* pred_pos = nullptr;
    const float* true_pos = nullptr;
    for (int i = 0; i < n_in; i++) {
        if (in_sizes[i] == POS_ELEMS) {
            if (!pred_pos)      pred_pos = (const float*)d_in[i];
            else if (!true_pos) true_pos = (const float*)d_in[i];
        }
    }
    if (!pred_pos || !true_pos) {  // fallback to documented order
        pred_pos = (const float*)d_in[2];
        true_pos = (const float*)d_in[3];
    }

    k1_cov  <<<BATCH, 512>>>(pred_pos, true_pos);
    k2_kabsch<<<1, 256>>>();
    k3_dist <<<BATCH, 512>>>(pred_pos, true_pos);
    k4_final<<<1, 256>>>((float*)d_out);
}

// round 8
// speedup vs baseline: 5.6497x; 5.6497x over previous
#include <cuda_runtime.h>
#include <cuda_bf16.h>
#include <math.h>

#define BATCH 256
#define NPTS  8192
#define THREADS 512
#define NCH   ((NPTS * 3) / 12)          // 2048 chunks of 4 points
#define ITERS (NCH / THREADS)            // 4
#define CLAMP_V 10.0f

// Scratch (no allocations allowed -> __device__ globals)
__device__ float d_RT[BATCH * 12];       // per batch: R row-major [9], t [3]
__device__ float d_partial[BATCH];       // per-batch clamped-distance sums
__device__ int   d_count;                // last-block counter (reset each run)

__device__ __forceinline__ float warpSum(float v) {
#pragma unroll
    for (int o = 16; o; o >>= 1) v += __shfl_down_sync(0xffffffffu, v, o);
    return v;
}

// ---------------------------------------------------------------------------
// fp32 Kabsch solve from the 15 reduced sums (single thread, ~2us).
// H = M - sumA sumB^T / N ; Jacobi eig of K = H^T H -> V, lam ; u_k = H v_k/sig
// R = sum_k s_k v_k u_k^T  (sign flip on SMALLEST sigma iff det(H) < 0)
// == V diag(1,1,s) U^T as in the reference. t = cB - R cA.
// ---------------------------------------------------------------------------
__device__ void kabsch_solve(const float* __restrict__ s, float* __restrict__ rt) {
    const float invN = 1.0f / (float)NPTS;
    float sA[3] = {s[0], s[1], s[2]};
    float sB[3] = {s[3], s[4], s[5]};
    float H[3][3];
#pragma unroll
    for (int i = 0; i < 3; i++)
#pragma unroll
        for (int j = 0; j < 3; j++)
            H[i][j] = s[6 + i * 3 + j] - sA[i] * sB[j] * invN;

    // K = H^T H (symmetric PSD)
    float K[3][3];
#pragma unroll
    for (int i = 0; i < 3; i++)
#pragma unroll
        for (int j = 0; j < 3; j++)
            K[i][j] = H[0][i]*H[0][j] + H[1][i]*H[1][j] + H[2][i]*H[2][j];

    float V[3][3] = {{1,0,0},{0,1,0},{0,0,1}};
    const int PP[3] = {0, 0, 1};
    const int QQ[3] = {1, 2, 2};
    for (int sweep = 0; sweep < 8; sweep++) {
#pragma unroll
        for (int pair = 0; pair < 3; pair++) {
            const int p = PP[pair], q = QQ[pair];
            float apq = K[p][q];
            if (fabsf(apq) <= 1e-10f * (fabsf(K[p][p]) + fabsf(K[q][q]))) continue;
            float theta = (K[q][q] - K[p][p]) / (2.0f * apq);
            float t = (theta >= 0.0f) ? 1.0f / (theta + sqrtf(1.0f + theta * theta))
                                      : 1.0f / (theta - sqrtf(1.0f + theta * theta));
            float c = rsqrtf(1.0f + t * t);
            float sn = t * c;
#pragma unroll
            for (int k = 0; k < 3; k++) {        // K <- K J
                float kp = K[k][p], kq = K[k][q];
                K[k][p] = c * kp - sn * kq;
                K[k][q] = sn * kp + c * kq;
            }
#pragma unroll
            for (int k = 0; k < 3; k++) {        // K <- J^T K
                float pk = K[p][k], qk = K[q][k];
                K[p][k] = c * pk - sn * qk;
                K[q][k] = sn * pk + c * qk;
            }
#pragma unroll
            for (int k = 0; k < 3; k++) {        // V <- V J
                float vp_ = V[k][p], vq_ = V[k][q];
                V[k][p] = c * vp_ - sn * vq_;
                V[k][q] = sn * vp_ + c * vq_;
            }
        }
    }

    float lam[3] = {K[0][0], K[1][1], K[2][2]};
    int imin = 0;
    if (lam[1] < lam[imin]) imin = 1;
    if (lam[2] < lam[imin]) imin = 2;

    float detH = H[0][0]*(H[1][1]*H[2][2] - H[1][2]*H[2][1])
               - H[0][1]*(H[1][0]*H[2][2] - H[1][2]*H[2][0])
               + H[0][2]*(H[1][0]*H[2][1] - H[1][1]*H[2][0]);

    float R[3][3] = {{0,0,0},{0,0,0},{0,0,0}};
#pragma unroll
    for (int k = 0; k < 3; k++) {
        float v0 = V[0][k], v1 = V[1][k], v2 = V[2][k];
        float hv0 = H[0][0]*v0 + H[0][1]*v1 + H[0][2]*v2;   // sigma_k * u_k
        float hv1 = H[1][0]*v0 + H[1][1]*v1 + H[1][2]*v2;
        float hv2 = H[2][0]*v0 + H[2][1]*v1 + H[2][2]*v2;
        float coef = rsqrtf(fmaxf(lam[k], 1e-30f));
        if (k == imin && detH < 0.0f) coef = -coef;
        R[0][0] += coef * v0 * hv0; R[0][1] += coef * v0 * hv1; R[0][2] += coef * v0 * hv2;
        R[1][0] += coef * v1 * hv0; R[1][1] += coef * v1 * hv1; R[1][2] += coef * v1 * hv2;
        R[2][0] += coef * v2 * hv0; R[2][1] += coef * v2 * hv1; R[2][2] += coef * v2 * hv2;
    }

    float cA0 = sA[0]*invN, cA1 = sA[1]*invN, cA2 = sA[2]*invN;
    float cB0 = sB[0]*invN, cB1 = sB[1]*invN, cB2 = sB[2]*invN;

#pragma unroll
    for (int i = 0; i < 3; i++)
#pragma unroll
        for (int j = 0; j < 3; j++)
            rt[i * 3 + j] = R[i][j];
    rt[9]  = cB0 - (R[0][0]*cA0 + R[0][1]*cA1 + R[0][2]*cA2);
    rt[10] = cB1 - (R[1][0]*cA0 + R[1][1]*cA1 + R[1][2]*cA2);
    rt[11] = cB2 - (R[2][0]*cA0 + R[2][1]*cA1 + R[2][2]*cA2);
}

// ---------------------------------------------------------------------------
// Kernel 1: per-batch reduction of 15 covariance terms + fused Kabsch solve.
// One block per batch, 512 threads, fully unrolled float4 loads.
// ---------------------------------------------------------------------------
__global__ __launch_bounds__(THREADS) void k1_cov(const float* __restrict__ pred,
                                                  const float* __restrict__ truep) {
    const int b = blockIdx.x;
    const float* pp = pred  + (size_t)b * NPTS * 3;
    const float* qq = truep + (size_t)b * NPTS * 3;

    float sA0=0.f,sA1=0.f,sA2=0.f,sB0=0.f,sB1=0.f,sB2=0.f;
    float m00=0.f,m01=0.f,m02=0.f,m10=0.f,m11=0.f,m12=0.f,m20=0.f,m21=0.f,m22=0.f;

    // Front-batch all loads: 4 fully-unrolled iterations x 6 float4 = 24 LDG.128
    float4 A[ITERS][3], Bv[ITERS][3];
#pragma unroll
    for (int it = 0; it < ITERS; it++) {
        const int c = threadIdx.x + it * THREADS;
        const float4* vp = reinterpret_cast<const float4*>(pp + c * 12);
        const float4* vq = reinterpret_cast<const float4*>(qq + c * 12);
        A[it][0] = vp[0]; A[it][1] = vp[1]; A[it][2] = vp[2];
        Bv[it][0] = vq[0]; Bv[it][1] = vq[1]; Bv[it][2] = vq[2];
    }
#pragma unroll
    for (int it = 0; it < ITERS; it++) {
        float4 a0 = A[it][0], a1 = A[it][1], a2 = A[it][2];
        float4 b0 = Bv[it][0], b1 = Bv[it][1], b2 = Bv[it][2];
        float px[4] = {a0.x, a0.w, a1.z, a2.y};
        float py[4] = {a0.y, a1.x, a1.w, a2.z};
        float pz[4] = {a0.z, a1.y, a2.x, a2.w};
        float qx[4] = {b0.x, b0.w, b1.z, b2.y};
        float qy[4] = {b0.y, b1.x, b1.w, b2.z};
        float qz[4] = {b0.z, b1.y, b2.x, b2.w};
#pragma unroll
        for (int i = 0; i < 4; i++) {
            sA0 += px[i]; sA1 += py[i]; sA2 += pz[i];
            sB0 += qx[i]; sB1 += qy[i]; sB2 += qz[i];
            m00 += px[i]*qx[i]; m01 += px[i]*qy[i]; m02 += px[i]*qz[i];
            m10 += py[i]*qx[i]; m11 += py[i]*qy[i]; m12 += py[i]*qz[i];
            m20 += pz[i]*qx[i]; m21 += pz[i]*qy[i]; m22 += pz[i]*qz[i];
        }
    }

    __shared__ float ws[16][15];
    __shared__ float sh15[15];
    float vals[15] = {sA0,sA1,sA2,sB0,sB1,sB2,m00,m01,m02,m10,m11,m12,m20,m21,m22};
    const int lane = threadIdx.x & 31, w = threadIdx.x >> 5;
#pragma unroll
    for (int q = 0; q < 15; q++) {
        float r = warpSum(vals[q]);
        if (lane == 0) ws[w][q] = r;
    }
    __syncthreads();
    if (threadIdx.x < 15) {
        float tot = 0.f;
#pragma unroll
        for (int i = 0; i < 16; i++) tot += ws[i][threadIdx.x];
        sh15[threadIdx.x] = tot;
    }
    __syncthreads();

    // Fused per-batch Kabsch solve (thread 0, ~2us, parallel across 256 blocks)
    if (threadIdx.x == 0) {
        kabsch_solve(sh15, &d_RT[b * 12]);
    }
}

// ---------------------------------------------------------------------------
// Kernel 2: apply (R, t), clamped distances, per-batch sum, fused final mean.
// aligned_j = sum_i p_i * R[i][j] + t[j]   (pred @ R, as in reference)
// ---------------------------------------------------------------------------
__global__ __launch_bounds__(THREADS) void k3_dist(const float* __restrict__ pred,
                                                   const float* __restrict__ truep,
                                                   float* __restrict__ out) {
    const int b = blockIdx.x;
    __shared__ float sRT[12];
    if (threadIdx.x < 12) sRT[threadIdx.x] = d_RT[b * 12 + threadIdx.x];
    __syncthreads();
    const float R00=sRT[0], R01=sRT[1], R02=sRT[2],
                R10=sRT[3], R11=sRT[4], R12=sRT[5],
                R20=sRT[6], R21=sRT[7], R22=sRT[8],
                t0 =sRT[9], t1 =sRT[10], t2 =sRT[11];

    const float* pp = pred  + (size_t)b * NPTS * 3;
    const float* qq = truep + (size_t)b * NPTS * 3;

    float acc = 0.f;
#pragma unroll
    for (int it = 0; it < ITERS; it++) {
        const int c = threadIdx.x + it * THREADS;
        const float4* vp = reinterpret_cast<const float4*>(pp + c * 12);
        const float4* vq = reinterpret_cast<const float4*>(qq + c * 12);
        float4 a0 = vp[0], a1 = vp[1], a2 = vp[2];
        float4 b0 = vq[0], b1 = vq[1], b2 = vq[2];
        float px[4] = {a0.x, a0.w, a1.z, a2.y};
        float py[4] = {a0.y, a1.x, a1.w, a2.z};
        float pz[4] = {a0.z, a1.y, a2.x, a2.w};
        float qx[4] = {b0.x, b0.w, b1.z, b2.y};
        float qy[4] = {b0.y, b1.x, b1.w, b2.z};
        float qz[4] = {b0.z, b1.y, b2.x, b2.w};
#pragma unroll
        for (int i = 0; i < 4; i++) {
            float dx = px[i]*R00 + py[i]*R10 + pz[i]*R20 + t0 - qx[i];
            float dy = px[i]*R01 + py[i]*R11 + pz[i]*R21 + t1 - qy[i];
            float dz = px[i]*R02 + py[i]*R12 + pz[i]*R22 + t2 - qz[i];
            float d = sqrtf(dx*dx + dy*dy + dz*dz);
            acc += fminf(d, CLAMP_V);
        }
    }

    __shared__ float ws[16];
    __shared__ bool  amLast;
    const int lane = threadIdx.x & 31, w = threadIdx.x >> 5;
    float r = warpSum(acc);
    if (lane == 0) ws[w] = r;
    __syncthreads();
    if (threadIdx.x == 0) {
        float t = 0.f;
#pragma unroll
        for (int i = 0; i < 16; i++) t += ws[i];
        d_partial[b] = t;
        __threadfence();
        int prev = atomicAdd(&d_count, 1);
        amLast = (prev == BATCH - 1);
    }
    __syncthreads();

    // Deterministic final reduce by the last-arriving block: fixed summation
    // order over d_partial[0..255] -> identical result regardless of which
    // block performs it.
    if (amLast) {
        __threadfence();
        float v = (threadIdx.x < BATCH) ? d_partial[threadIdx.x] : 0.f;
        __shared__ float fs[16];
        float rr = warpSum(v);
        if (lane == 0) fs[w] = rr;
        __syncthreads();
        if (threadIdx.x == 0) {
            float tot = 0.f;
#pragma unroll
            for (int i = 0; i < 8; i++) tot += fs[i];   // only first 8 warps hold BATCH=256
            out[0] = tot / ((float)BATCH * (float)NPTS);
            d_count = 0;   // reset for next graph replay
        }
    }
}

extern "C" void kernel_launch(void* const* d_in, const int* in_sizes, int n_in,
                              void* d_out, int out_size) {
    // Inputs in metadata order: pred_frames, true_frames, pred_pos, true_pos.
    // Select the two [B,N,3] arrays (size B*N*3) in order; frames stay untouched.
    const int POS_ELEMS = BATCH * NPTS * 3;
    const float* pred_pos = nullptr;
    const float* true_pos = nullptr;
    for (int i = 0; i < n_in; i++) {
        if (in_sizes[i] == POS_ELEMS) {
            if (!pred_pos)      pred_pos = (const float*)d_in[i];
            else if (!true_pos) true_pos = (const float*)d_in[i];
        }
    }
    if (!pred_pos || !true_pos) {
        pred_pos = (const float*)d_in[2];
        true_pos = (const float*)d_in[3];
    }

    k1_cov <<<BATCH, THREADS>>>(pred_pos, true_pos);
    k3_dist<<<BATCH, THREADS>>>(pred_pos, true_pos, (float*)d_out);
}